// round 2
// baseline (speedup 1.0000x reference)
#include <cuda_runtime.h>

#define NB      40
#define C       128
#define BATCH   4
#define TMAX    8192
#define SKIP_T  4096
#define TN      64

// ---------------- device scratch (no allocations allowed) ----------------
__device__ float g_x0[BATCH * C * TMAX];
__device__ float g_x1[BATCH * C * TMAX];
__device__ float g_wA[NB * 256 * C];   // [blk][k(0..255)][m]  k<128: tap0, k>=128: tap1
__device__ float g_wR[NB * C * C];     // [blk][k][m] (transposed w_res)
__device__ float g_wS[NB * C * C];     // [blk][k][m] (transposed w_skip)

// ---------------- packed f32x2 helpers (Blackwell FFMA2) ----------------
__device__ __forceinline__ unsigned long long pack2(float lo, float hi) {
    unsigned long long r;
    asm("mov.b64 %0, {%1, %2};" : "=l"(r) : "f"(lo), "f"(hi));
    return r;
}
__device__ __forceinline__ void unpack2(unsigned long long v, float& lo, float& hi) {
    asm("mov.b64 {%0, %1}, %2;" : "=f"(lo), "=f"(hi) : "l"(v));
}
__device__ __forceinline__ void ffma2(unsigned long long& d,
                                      unsigned long long a,
                                      unsigned long long b) {
    asm("fma.rn.f32x2 %0, %1, %2, %0;" : "+l"(d) : "l"(a), "l"(b));
}

// ---------------- weight re-layout: [k][m] K-major, taps merged ----------------
__global__ void prep_weights(const float* __restrict__ w_dil,
                             const float* __restrict__ w_res,
                             const float* __restrict__ w_skip) {
    int idx = blockIdx.x * blockDim.x + threadIdx.x;
    if (idx < NB * 256 * C) {
        int m   = idx & 127;
        int k   = (idx >> 7) & 255;
        int blk = idx >> 15;
        float v;
        if (k < 128) v = w_dil[(((size_t)blk * C + m) * C + k) * 2 + 0];
        else         v = w_dil[(((size_t)blk * C + m) * C + (k - 128)) * 2 + 1];
        g_wA[idx] = v;
    }
    if (idx < NB * C * C) {
        int m   = idx & 127;
        int k   = (idx >> 7) & 127;
        int blk = idx >> 14;
        g_wR[idx] = w_res[((size_t)blk * C + m) * C + k];
        g_wS[idx] = w_skip[((size_t)blk * C + m) * C + k];
    }
}

// ---------------- fused per-block kernel ----------------
// CTA tile: all 128 out-channels x TN=64 time steps, for one batch element.
// Phase 1: Y = W0 @ x[:, t] + W1 @ x[:, t+d]          (K = 256)
// Gate:    G = tanh(Y) * sigmoid(Y)                    -> smem
// Phase 2: R = Wres @ G, S = Wskip @ G                 (K = 128, fused)
// Epilogue: xout = R + b_res + x[:, t+d];  skip_out last 4096 cols of S + b_skip
__global__ __launch_bounds__(256, 2)
void wavenet_block(const float* __restrict__ xin, float* __restrict__ xout,
                   const float* __restrict__ wA, const float* __restrict__ wR,
                   const float* __restrict__ wS,
                   const float* __restrict__ brs, const float* __restrict__ bsk,
                   float* __restrict__ skip_out,
                   int d, int Sin, int Tout, int Sout)
{
    __shared__ __align__(16) float Gs[C * TN];      // 32 KB gated activations
    __shared__ __align__(16) float AsR[16 * C];     // 8 KB (phase1: A chunk / phase2: Wres chunk)
    __shared__ __align__(16) float AsS[16 * C];     // 8 KB (phase1: B chunk / phase2: Wskip chunk)
    float* As = AsR;
    float* Bs = AsS;

    const int tid = threadIdx.x;
    const int tx  = tid & 15;        // n group
    const int ty  = tid >> 4;        // m group
    const int n0  = tx * 4;
    const int m0  = ty * 8;
    const int t0  = blockIdx.x * TN;
    const int b   = blockIdx.y;

    const float* xb = xin + (size_t)b * C * Sin;

    // ---------------- Phase 1 ----------------
    unsigned long long acc[4][4];
    #pragma unroll
    for (int i = 0; i < 4; i++)
        #pragma unroll
        for (int j = 0; j < 4; j++) acc[i][j] = 0ull;

    for (int kc = 0; kc < 256; kc += 16) {
        // stage A chunk (16 x 128), coalesced float4
        {
            const float4* w4 = (const float4*)(wA + (size_t)kc * C);
            float4* a4 = (float4*)As;
            a4[tid * 2]     = w4[tid * 2];
            a4[tid * 2 + 1] = w4[tid * 2 + 1];
        }
        // stage B chunk (16 x 64): thread -> kk = tid>>4, n = (tid&15)*4
        {
            int kk = tid >> 4;
            int nb = (tid & 15) * 4;
            int kg = kc + kk;
            const float* src = (kg < 128) ? (xb + (size_t)kg * Sin + t0)
                                          : (xb + (size_t)(kg - 128) * Sin + t0 + d);
            float* dst = Bs + kk * TN + nb;
            #pragma unroll
            for (int j = 0; j < 4; j++) {
                int t = t0 + nb + j;
                dst[j] = (t < Tout) ? src[nb + j] : 0.f;
            }
        }
        __syncthreads();
        #pragma unroll
        for (int kk = 0; kk < 16; kk++) {
            const ulonglong2* av = (const ulonglong2*)(As + kk * C + m0);
            ulonglong2 a0 = av[0];
            ulonglong2 a1 = av[1];
            unsigned long long ap[4] = {a0.x, a0.y, a1.x, a1.y};
            float4 bv = *(const float4*)(Bs + kk * TN + n0);
            unsigned long long bb[4];
            bb[0] = pack2(bv.x, bv.x);
            bb[1] = pack2(bv.y, bv.y);
            bb[2] = pack2(bv.z, bv.z);
            bb[3] = pack2(bv.w, bv.w);
            #pragma unroll
            for (int i = 0; i < 4; i++)
                #pragma unroll
                for (int j = 0; j < 4; j++)
                    ffma2(acc[i][j], ap[i], bb[j]);
        }
        __syncthreads();
    }

    // ---------------- gate -> Gs ----------------
    #pragma unroll
    for (int i = 0; i < 4; i++) {
        #pragma unroll
        for (int j = 0; j < 4; j++) {
            float ylo, yhi;
            unpack2(acc[i][j], ylo, yhi);
            float glo = tanhf(ylo) * (1.f / (1.f + __expf(-ylo)));
            float ghi = tanhf(yhi) * (1.f / (1.f + __expf(-yhi)));
            Gs[(m0 + 2 * i)     * TN + n0 + j] = glo;
            Gs[(m0 + 2 * i + 1) * TN + n0 + j] = ghi;
        }
    }
    __syncthreads();

    // ---------------- Phase 2 (res + skip fused) ----------------
    unsigned long long accR[4][4], accS[4][4];
    #pragma unroll
    for (int i = 0; i < 4; i++)
        #pragma unroll
        for (int j = 0; j < 4; j++) { accR[i][j] = 0ull; accS[i][j] = 0ull; }

    for (int kc = 0; kc < 128; kc += 16) {
        {
            const float4* r4 = (const float4*)(wR + (size_t)kc * C);
            const float4* s4 = (const float4*)(wS + (size_t)kc * C);
            float4* ar4 = (float4*)AsR;
            float4* as4 = (float4*)AsS;
            ar4[tid * 2]     = r4[tid * 2];
            ar4[tid * 2 + 1] = r4[tid * 2 + 1];
            as4[tid * 2]     = s4[tid * 2];
            as4[tid * 2 + 1] = s4[tid * 2 + 1];
        }
        __syncthreads();
        #pragma unroll
        for (int kk = 0; kk < 16; kk++) {
            const ulonglong2* arv = (const ulonglong2*)(AsR + kk * C + m0);
            const ulonglong2* asv = (const ulonglong2*)(AsS + kk * C + m0);
            ulonglong2 ar0 = arv[0], ar1 = arv[1];
            ulonglong2 as0 = asv[0], as1 = asv[1];
            unsigned long long apR[4] = {ar0.x, ar0.y, ar1.x, ar1.y};
            unsigned long long apS[4] = {as0.x, as0.y, as1.x, as1.y};
            float4 bv = *(const float4*)(Gs + (kc + kk) * TN + n0);
            unsigned long long bb[4];
            bb[0] = pack2(bv.x, bv.x);
            bb[1] = pack2(bv.y, bv.y);
            bb[2] = pack2(bv.z, bv.z);
            bb[3] = pack2(bv.w, bv.w);
            #pragma unroll
            for (int i = 0; i < 4; i++)
                #pragma unroll
                for (int j = 0; j < 4; j++) {
                    ffma2(accR[i][j], apR[i], bb[j]);
                    ffma2(accS[i][j], apS[i], bb[j]);
                }
        }
        __syncthreads();
    }

    // ---------------- epilogue ----------------
    const int skip_base = Tout - SKIP_T;
    const float* xres = xb + d;
    const int t = t0 + n0;
    #pragma unroll
    for (int i = 0; i < 4; i++) {
        const int mA = m0 + 2 * i;
        const int mB = mA + 1;
        const float brA = brs[mA], brB = brs[mB];
        const float bsA = bsk[mA], bsB = bsk[mB];
        float rA[4], rB[4], sA[4], sB[4];
        #pragma unroll
        for (int j = 0; j < 4; j++) {
            unpack2(accR[i][j], rA[j], rB[j]);
            unpack2(accS[i][j], sA[j], sB[j]);
        }
        if (t + 3 < Tout) {
            float4 oA, oB;
            oA.x = rA[0] + brA + xres[(size_t)mA * Sin + t + 0];
            oA.y = rA[1] + brA + xres[(size_t)mA * Sin + t + 1];
            oA.z = rA[2] + brA + xres[(size_t)mA * Sin + t + 2];
            oA.w = rA[3] + brA + xres[(size_t)mA * Sin + t + 3];
            oB.x = rB[0] + brB + xres[(size_t)mB * Sin + t + 0];
            oB.y = rB[1] + brB + xres[(size_t)mB * Sin + t + 1];
            oB.z = rB[2] + brB + xres[(size_t)mB * Sin + t + 2];
            oB.w = rB[3] + brB + xres[(size_t)mB * Sin + t + 3];
            *(float4*)(xout + ((size_t)b * C + mA) * Sout + t) = oA;
            *(float4*)(xout + ((size_t)b * C + mB) * Sout + t) = oB;
            #pragma unroll
            for (int j = 0; j < 4; j++) {
                int ts = t + j - skip_base;
                if (ts >= 0) {
                    skip_out[((size_t)b * C + mA) * SKIP_T + ts] = sA[j] + bsA;
                    skip_out[((size_t)b * C + mB) * SKIP_T + ts] = sB[j] + bsB;
                }
            }
        } else {
            for (int j = 0; j < 4; j++) {
                int tt = t + j;
                if (tt < Tout) {
                    xout[((size_t)b * C + mA) * Sout + tt] = rA[j] + brA + xres[(size_t)mA * Sin + tt];
                    xout[((size_t)b * C + mB) * Sout + tt] = rB[j] + brB + xres[(size_t)mB * Sin + tt];
                    int ts = tt - skip_base;
                    if (ts >= 0) {
                        skip_out[((size_t)b * C + mA) * SKIP_T + ts] = sA[j] + bsA;
                        skip_out[((size_t)b * C + mB) * SKIP_T + ts] = sB[j] + bsB;
                    }
                }
            }
        }
    }
}

// ---------------- host ----------------
static const int DIL[NB] = {
    1, 2, 4, 8, 16, 32, 64, 128, 256, 512,
    1, 2, 4, 8, 16, 32, 64, 128, 256, 512,
    1, 2, 4, 8, 16, 32, 64, 128, 256, 512,
    1, 2, 4, 8, 16, 32, 64, 128, 256, 512
};

extern "C" void kernel_launch(void* const* d_in, const int* in_sizes, int n_in,
                              void* d_out, int out_size)
{
    const float* x      = (const float*)d_in[0];
    const float* w_dil  = (const float*)d_in[1];
    const float* w_res  = (const float*)d_in[2];
    const float* b_res  = (const float*)d_in[3];
    const float* w_skip = (const float*)d_in[4];
    const float* b_skip = (const float*)d_in[5];
    float* out = (float*)d_out;

    float *xb0, *xb1, *wA, *wR, *wS;
    cudaGetSymbolAddress((void**)&xb0, g_x0);
    cudaGetSymbolAddress((void**)&xb1, g_x1);
    cudaGetSymbolAddress((void**)&wA,  g_wA);
    cudaGetSymbolAddress((void**)&wR,  g_wR);
    cudaGetSymbolAddress((void**)&wS,  g_wS);

    {
        int total = NB * 256 * C;
        prep_weights<<<(total + 255) / 256, 256>>>(w_dil, w_res, w_skip);
    }

    int Tin = TMAX;
    int Sin = TMAX;
    const float* cur = x;
    for (int L = 0; L < NB; L++) {
        int dd   = DIL[L];
        int Tout = Tin - dd;
        int Sout = (Tout + 3) & ~3;
        float* xo = (L & 1) ? xb1 : xb0;
        dim3 grid((Tout + TN - 1) / TN, BATCH);
        wavenet_block<<<grid, 256>>>(
            cur, xo,
            wA + (size_t)L * 256 * C,
            wR + (size_t)L * C * C,
            wS + (size_t)L * C * C,
            b_res + (size_t)L * C,
            b_skip + (size_t)L * C,
            out + (size_t)L * BATCH * C * SKIP_T,
            dd, Sin, Tout, Sout);
        cur = xo;
        Tin = Tout;
        Sin = Sout;
    }
}

// round 4
// speedup vs baseline: 1.4928x; 1.4928x over previous
#include <cuda_runtime.h>
#include <cuda_bf16.h>
#include <cstdint>

#define NB      40
#define C       128
#define BATCH   4
#define TMAX    8192
#define SKIP_T  4096
#define TN      64

// ======================= device scratch (no allocs allowed) =======================
__device__ float g_x0[BATCH * C * TMAX];
__device__ float g_x1[BATCH * C * TMAX];
// A-operand fragments, packed per-lane in mma register order. Each slot = 2 x uint4 (hi, lo).
__device__ uint4 g_wAf[NB * 16 * 8 * 32 * 2];   // GEMM1: 16 ksteps
__device__ uint4 g_wRf[NB *  8 * 8 * 32 * 2];   // res:   8 ksteps
__device__ uint4 g_wSf[NB *  8 * 8 * 32 * 2];   // skip:  8 ksteps

#define SWZ(o) ((uint32_t)(o) ^ ((((uint32_t)(o)) >> 3) & 0x70u))

__device__ __forceinline__ uint32_t smem_to_u32(const void* p) {
    uint32_t a;
    asm("{ .reg .u64 t; cvta.to.shared.u64 t, %1; cvt.u32.u64 %0, t; }" : "=r"(a) : "l"(p));
    return a;
}

__device__ __forceinline__ void mma_bf16(float* c, const uint32_t* a, const uint32_t* b) {
    asm volatile("mma.sync.aligned.m16n8k16.row.col.f32.bf16.bf16.f32 "
        "{%0,%1,%2,%3}, {%4,%5,%6,%7}, {%8,%9}, {%0,%1,%2,%3};"
        : "+f"(c[0]), "+f"(c[1]), "+f"(c[2]), "+f"(c[3])
        : "r"(a[0]), "r"(a[1]), "r"(a[2]), "r"(a[3]), "r"(b[0]), "r"(b[1]));
}

__device__ __forceinline__ void ldsm_x4(uint32_t* r, uint32_t addr) {
    asm volatile("ldmatrix.sync.aligned.m8n8.x4.shared.b16 {%0,%1,%2,%3}, [%4];"
        : "=r"(r[0]), "=r"(r[1]), "=r"(r[2]), "=r"(r[3]) : "r"(addr));
}

__device__ __forceinline__ uint32_t pk2(float a, float b) {
    __nv_bfloat162 t = __floats2bfloat162_rn(a, b);
    return *reinterpret_cast<uint32_t*>(&t);
}
__device__ __forceinline__ void hilo(float v, float& h, float& l) {
    h = __bfloat162float(__float2bfloat16(v));
    l = v - h;
}

// gate(y) = tanh(y) * sigmoid(y), exp-based (accurate, no NaN at extremes)
__device__ __forceinline__ float gatef(float y) {
    float ay = fabsf(y);
    float e2 = __expf(-2.f * ay);
    float th = (1.f - e2) / (1.f + e2);          // tanh(|y|)
    th = copysignf(th, y);
    float sg = 1.f / (1.f + __expf(-y));
    return th * sg;
}

// ======================= prep: pack A fragments in register order =======================
// slot = [blk][ks][mt(8)][lane(32)]; regs a0..a3 per mma m16n8k16 A layout:
//   r = lane>>2, c2 = (lane&3)*2
//   a0=(r, c2,c2+1)  a1=(r+8, c2)  a2=(r, c2+8)  a3=(r+8, c2+8)
__global__ void prep_frags(const float* __restrict__ w_dil,
                           const float* __restrict__ w_res,
                           const float* __restrict__ w_skip) {
    int idx = blockIdx.x * blockDim.x + threadIdx.x;
    // ---- GEMM1 weights (K=256: tap0 ch 0..127, tap1 ch 128..255) ----
    if (idx < NB * 16 * 8 * 32) {
        int lane = idx & 31, mt = (idx >> 5) & 7, ks = (idx >> 8) & 15, blk = idx >> 12;
        int r = lane >> 2, c2 = (lane & 3) * 2;
        int mr[2] = { mt * 16 + r, mt * 16 + r + 8 };
        int kc[2] = { ks * 16 + c2, ks * 16 + c2 + 8 };
        float h[2][2][2], l[2][2][2];
        #pragma unroll
        for (int mi = 0; mi < 2; mi++)
            #pragma unroll
            for (int kh = 0; kh < 2; kh++)
                #pragma unroll
                for (int e = 0; e < 2; e++) {
                    int k = kc[kh] + e;
                    int tap = k >> 7, ch = k & 127;
                    float v = w_dil[(((size_t)blk * C + mr[mi]) * C + ch) * 2 + tap];
                    hilo(v, h[mi][kh][e], l[mi][kh][e]);
                }
        uint4 hv = { pk2(h[0][0][0], h[0][0][1]), pk2(h[1][0][0], h[1][0][1]),
                     pk2(h[0][1][0], h[0][1][1]), pk2(h[1][1][0], h[1][1][1]) };
        uint4 lv = { pk2(l[0][0][0], l[0][0][1]), pk2(l[1][0][0], l[1][0][1]),
                     pk2(l[0][1][0], l[0][1][1]), pk2(l[1][1][0], l[1][1][1]) };
        g_wAf[(size_t)idx * 2]     = hv;
        g_wAf[(size_t)idx * 2 + 1] = lv;
    }
    // ---- res / skip weights (K=128) ----
    if (idx < NB * 8 * 8 * 32) {
        int lane = idx & 31, mt = (idx >> 5) & 7, ks = (idx >> 8) & 7, blk = idx >> 11;
        int r = lane >> 2, c2 = (lane & 3) * 2;
        int mr[2] = { mt * 16 + r, mt * 16 + r + 8 };
        int kc[2] = { ks * 16 + c2, ks * 16 + c2 + 8 };
        float hR[2][2][2], lR[2][2][2], hS[2][2][2], lS[2][2][2];
        #pragma unroll
        for (int mi = 0; mi < 2; mi++)
            #pragma unroll
            for (int kh = 0; kh < 2; kh++)
                #pragma unroll
                for (int e = 0; e < 2; e++) {
                    int k = kc[kh] + e;
                    float vr = w_res [((size_t)blk * C + mr[mi]) * C + k];
                    float vs = w_skip[((size_t)blk * C + mr[mi]) * C + k];
                    hilo(vr, hR[mi][kh][e], lR[mi][kh][e]);
                    hilo(vs, hS[mi][kh][e], lS[mi][kh][e]);
                }
        uint4 v;
        v = make_uint4(pk2(hR[0][0][0],hR[0][0][1]), pk2(hR[1][0][0],hR[1][0][1]),
                       pk2(hR[0][1][0],hR[0][1][1]), pk2(hR[1][1][0],hR[1][1][1]));
        g_wRf[(size_t)idx * 2] = v;
        v = make_uint4(pk2(lR[0][0][0],lR[0][0][1]), pk2(lR[1][0][0],lR[1][0][1]),
                       pk2(lR[0][1][0],lR[0][1][1]), pk2(lR[1][1][0],lR[1][1][1]));
        g_wRf[(size_t)idx * 2 + 1] = v;
        v = make_uint4(pk2(hS[0][0][0],hS[0][0][1]), pk2(hS[1][0][0],hS[1][0][1]),
                       pk2(hS[0][1][0],hS[0][1][1]), pk2(hS[1][1][0],hS[1][1][1]));
        g_wSf[(size_t)idx * 2] = v;
        v = make_uint4(pk2(lS[0][0][0],lS[0][0][1]), pk2(lS[1][0][0],lS[1][0][1]),
                       pk2(lS[0][1][0],lS[0][1][1]), pk2(lS[1][1][0],lS[1][1][1]));
        g_wSf[(size_t)idx * 2 + 1] = v;
    }
}

// ======================= fused block kernel =======================
// smem layout (dynamic, 64KB):
//   B1 hi: [0, 32K)   4 chunks of [64 n rows][64 k cols] bf16, SW128, 8192B each
//   B1 lo: [32K, 64K)
//   G  hi: [0, 16K)   2 chunks (reuses B1 region after phase-1 sync)
//   G  lo: [16K, 32K)
#define SM_B1H 0u
#define SM_B1L 32768u
#define SM_GH  0u
#define SM_GL  16384u
#define SMEM_SZ 65536

struct Frag { uint32_t a[4]; };
__device__ __forceinline__ Frag ldfrag(const uint4* p) {
    uint4 v = __ldg(p);
    Frag f; f.a[0] = v.x; f.a[1] = v.y; f.a[2] = v.z; f.a[3] = v.w;
    return f;
}

__global__ __launch_bounds__(256, 1)
void wn_hmma(const float* __restrict__ xin, float* __restrict__ xout,
             const uint4* __restrict__ Af, const uint4* __restrict__ Rf,
             const uint4* __restrict__ Sf,
             const float* __restrict__ brs, const float* __restrict__ bsk,
             float* __restrict__ skip_out,
             int d, int Sin, int Tout, int Sout)
{
    extern __shared__ __align__(1024) char smem[];
    const uint32_t sbase = smem_to_u32(smem);
    const int tid  = threadIdx.x;
    const int wid  = tid >> 5;
    const int lane = tid & 31;
    const int t0   = blockIdx.x * TN;
    const int b    = blockIdx.y;
    const int mt   = wid;                 // each warp: 16 m-rows x 64 n
    const int m0   = mt * 16;

    const float* xb = xin + (size_t)b * C * Sin;

    // ---------------- stage B1: x taps -> [n][k] bf16 hi/lo, swizzled ----------------
    {
        const int kp = tid & 127;         // k pair index: k = 2kp, 2kp+1
        const int th = tid >> 7;          // t half: rows th*32 .. +31
        const int k0 = kp * 2;
        const int g  = k0 >> 6;
        const int kc = (k0 & 63) * 2;     // byte col of the 4B word (holds both k)
        const int off = (k0 >= 128) ? d : 0;
        const int ch0 = k0 & 127, ch1 = (k0 + 1) & 127;
        const float* s0 = xb + (size_t)ch0 * Sin + t0 + off;
        const float* s1 = xb + (size_t)ch1 * Sin + t0 + off;
        const int tr0 = th * 32;
        char* dh = smem + SM_B1H + g * 8192 + 0;
        char* dl = smem + SM_B1L + g * 8192 + 0;
        bool vec = (t0 + TN <= Tout) && (((t0 + off) & 3) == 0);
        if (vec) {
            #pragma unroll
            for (int q = 0; q < 8; q++) {
                int tt = tr0 + q * 4;
                float4 a = __ldg((const float4*)(s0 + tt));
                float4 bq = __ldg((const float4*)(s1 + tt));
                float av[4] = {a.x, a.y, a.z, a.w};
                float bv[4] = {bq.x, bq.y, bq.z, bq.w};
                #pragma unroll
                for (int j = 0; j < 4; j++) {
                    float ha, la, hb, lb;
                    hilo(av[j], ha, la); hilo(bv[j], hb, lb);
                    uint32_t o = SWZ((tt + j) * 128 + kc);
                    *(uint32_t*)(dh + o) = pk2(ha, hb);
                    *(uint32_t*)(dl + o) = pk2(la, lb);
                }
            }
        } else {
            #pragma unroll 4
            for (int j = 0; j < 32; j++) {
                int tt = tr0 + j;
                float av = (t0 + tt < Tout) ? __ldg(s0 + tt) : 0.f;
                float bv = (t0 + tt < Tout) ? __ldg(s1 + tt) : 0.f;
                float ha, la, hb, lb;
                hilo(av, ha, la); hilo(bv, hb, lb);
                uint32_t o = SWZ(tt * 128 + kc);
                *(uint32_t*)(dh + o) = pk2(ha, hb);
                *(uint32_t*)(dl + o) = pk2(la, lb);
            }
        }
    }
    __syncthreads();

    // per-lane ldmatrix address components: mi = lane>>3
    const int lrow = (((lane >> 4) & 1) << 3) + (lane & 7); // (mi>>1)*8 + lane&7
    const int lcol = (lane >> 3) & 1;                        // mi&1

    // ---------------- phase 1: Y = W1 @ [x_tap0 ; x_tap1], K=256 ----------------
    float acc1[8][4];
    #pragma unroll
    for (int j = 0; j < 8; j++)
        #pragma unroll
        for (int q = 0; q < 4; q++) acc1[j][q] = 0.f;

    {
        const uint4* fp = Af + (((0 * 8 + mt) * 32 + lane) << 1);
        Frag aH = ldfrag(fp), aL = ldfrag(fp + 1);
        for (int ks = 0; ks < 16; ks++) {
            Frag nH, nL;
            if (ks < 15) {
                const uint4* np = Af + ((((ks + 1) * 8 + mt) * 32 + lane) << 1);
                nH = ldfrag(np); nL = ldfrag(np + 1);
            }
            const int g = ks >> 2, kk = ks & 3;
            const uint32_t cbh = sbase + SM_B1H + g * 8192;
            const uint32_t cbl = sbase + SM_B1L + g * 8192;
            uint32_t bh[8][2], bl[8][2];
            #pragma unroll
            for (int jp = 0; jp < 4; jp++) {
                uint32_t off = ((jp * 16 + lrow) << 7) + (kk << 5) + (lcol << 4);
                uint32_t r[4];
                ldsm_x4(r, cbh + SWZ(off));
                bh[2*jp][0]=r[0]; bh[2*jp][1]=r[1]; bh[2*jp+1][0]=r[2]; bh[2*jp+1][1]=r[3];
                ldsm_x4(r, cbl + SWZ(off));
                bl[2*jp][0]=r[0]; bl[2*jp][1]=r[1]; bl[2*jp+1][0]=r[2]; bl[2*jp+1][1]=r[3];
            }
            #pragma unroll
            for (int j = 0; j < 8; j++) mma_bf16(acc1[j], aH.a, bh[j]);
            #pragma unroll
            for (int j = 0; j < 8; j++) mma_bf16(acc1[j], aH.a, bl[j]);
            #pragma unroll
            for (int j = 0; j < 8; j++) mma_bf16(acc1[j], aL.a, bh[j]);
            aH = nH; aL = nL;
        }
    }
    __syncthreads();   // all warps done reading B1 before G overwrites it

    // ---------------- gate -> G smem [n][k=mid] hi/lo ----------------
    {
        const int r = lane >> 2, c2 = (lane & 3) * 2;
        #pragma unroll
        for (int j = 0; j < 8; j++) {
            #pragma unroll
            for (int q = 0; q < 4; q++) {
                int m = m0 + r + ((q >> 1) << 3);
                int n = j * 8 + c2 + (q & 1);
                float gv = gatef(acc1[j][q]);
                float h, l; hilo(gv, h, l);
                uint32_t o = (uint32_t)(m >> 6) * 8192u + SWZ(n * 128 + (m & 63) * 2);
                *(__nv_bfloat16*)(smem + SM_GH + o) = __float2bfloat16(h);
                *(__nv_bfloat16*)(smem + SM_GL + o) = __float2bfloat16(l);
            }
        }
    }
    __syncthreads();

    // ---------------- phase 2: R = Wres@G, S = Wskip@G, K=128 ----------------
    float accR[8][4], accS[8][4];
    #pragma unroll
    for (int j = 0; j < 8; j++)
        #pragma unroll
        for (int q = 0; q < 4; q++) { accR[j][q] = 0.f; accS[j][q] = 0.f; }

    {
        const uint4* rp = Rf + (((0 * 8 + mt) * 32 + lane) << 1);
        const uint4* sp = Sf + (((0 * 8 + mt) * 32 + lane) << 1);
        Frag rH = ldfrag(rp), rL = ldfrag(rp + 1);
        Frag sH = ldfrag(sp), sL = ldfrag(sp + 1);
        for (int ks = 0; ks < 8; ks++) {
            Frag nrH, nrL, nsH, nsL;
            if (ks < 7) {
                const uint4* nrp = Rf + ((((ks + 1) * 8 + mt) * 32 + lane) << 1);
                const uint4* nsp = Sf + ((((ks + 1) * 8 + mt) * 32 + lane) << 1);
                nrH = ldfrag(nrp); nrL = ldfrag(nrp + 1);
                nsH = ldfrag(nsp); nsL = ldfrag(nsp + 1);
            }
            const int g = ks >> 2, kk = ks & 3;
            const uint32_t cbh = sbase + SM_GH + g * 8192;
            const uint32_t cbl = sbase + SM_GL + g * 8192;
            uint32_t bh[8][2], bl[8][2];
            #pragma unroll
            for (int jp = 0; jp < 4; jp++) {
                uint32_t off = ((jp * 16 + lrow) << 7) + (kk << 5) + (lcol << 4);
                uint32_t r[4];
                ldsm_x4(r, cbh + SWZ(off));
                bh[2*jp][0]=r[0]; bh[2*jp][1]=r[1]; bh[2*jp+1][0]=r[2]; bh[2*jp+1][1]=r[3];
                ldsm_x4(r, cbl + SWZ(off));
                bl[2*jp][0]=r[0]; bl[2*jp][1]=r[1]; bl[2*jp+1][0]=r[2]; bl[2*jp+1][1]=r[3];
            }
            #pragma unroll
            for (int j = 0; j < 8; j++) mma_bf16(accR[j], rH.a, bh[j]);
            #pragma unroll
            for (int j = 0; j < 8; j++) mma_bf16(accS[j], sH.a, bh[j]);
            #pragma unroll
            for (int j = 0; j < 8; j++) mma_bf16(accR[j], rH.a, bl[j]);
            #pragma unroll
            for (int j = 0; j < 8; j++) mma_bf16(accS[j], sH.a, bl[j]);
            #pragma unroll
            for (int j = 0; j < 8; j++) mma_bf16(accR[j], rL.a, bh[j]);
            #pragma unroll
            for (int j = 0; j < 8; j++) mma_bf16(accS[j], sL.a, bh[j]);
            rH = nrH; rL = nrL; sH = nsH; sL = nsL;
        }
    }

    // ---------------- epilogue ----------------
    {
        const int r = lane >> 2, c2 = (lane & 3) * 2;
        const int mA = m0 + r, mB = mA + 8;
        const float brA = brs[mA], brB = brs[mB];
        const float bsA = bsk[mA], bsB = bsk[mB];
        const float* xrA = xb + (size_t)mA * Sin + d;
        const float* xrB = xb + (size_t)mB * Sin + d;
        float* xoA = xout + ((size_t)b * C + mA) * Sout;
        float* xoB = xout + ((size_t)b * C + mB) * Sout;
        float* soA = skip_out + ((size_t)b * C + mA) * SKIP_T;
        float* soB = skip_out + ((size_t)b * C + mB) * SKIP_T;
        const int skip_base = Tout - SKIP_T;
        #pragma unroll
        for (int j = 0; j < 8; j++) {
            int t = t0 + j * 8 + c2;
            #pragma unroll
            for (int e = 0; e < 2; e++) {
                int tt = t + e;
                if (tt < Tout) {
                    xoA[tt] = accR[j][e] + brA + __ldg(xrA + tt);
                    xoB[tt] = accR[j][2 + e] + brB + __ldg(xrB + tt);
                    int ts = tt - skip_base;
                    if (ts >= 0) {
                        soA[ts] = accS[j][e] + bsA;
                        soB[ts] = accS[j][2 + e] + bsB;
                    }
                }
            }
        }
    }
}

// ======================= host =======================
static const int DIL[NB] = {
    1, 2, 4, 8, 16, 32, 64, 128, 256, 512,
    1, 2, 4, 8, 16, 32, 64, 128, 256, 512,
    1, 2, 4, 8, 16, 32, 64, 128, 256, 512,
    1, 2, 4, 8, 16, 32, 64, 128, 256, 512
};

extern "C" void kernel_launch(void* const* d_in, const int* in_sizes, int n_in,
                              void* d_out, int out_size)
{
    const float* x      = (const float*)d_in[0];
    const float* w_dil  = (const float*)d_in[1];
    const float* w_res  = (const float*)d_in[2];
    const float* b_res  = (const float*)d_in[3];
    const float* w_skip = (const float*)d_in[4];
    const float* b_skip = (const float*)d_in[5];
    float* out = (float*)d_out;

    float *xb0, *xb1;
    uint4 *wAf, *wRf, *wSf;
    cudaGetSymbolAddress((void**)&xb0, g_x0);
    cudaGetSymbolAddress((void**)&xb1, g_x1);
    cudaGetSymbolAddress((void**)&wAf, g_wAf);
    cudaGetSymbolAddress((void**)&wRf, g_wRf);
    cudaGetSymbolAddress((void**)&wSf, g_wSf);

    cudaFuncSetAttribute(wn_hmma, cudaFuncAttributeMaxDynamicSharedMemorySize, SMEM_SZ);

    {
        int total = NB * 16 * 8 * 32;   // 163840 (covers wR/wS ranges too)
        prep_frags<<<(total + 255) / 256, 256>>>(w_dil, w_res, w_skip);
    }

    int Tin = TMAX;
    int Sin = TMAX;
    const float* cur = x;
    for (int L = 0; L < NB; L++) {
        int dd   = DIL[L];
        int Tout = Tin - dd;
        int Sout = (Tout + 3) & ~3;
        float* xo = (L & 1) ? xb1 : xb0;
        dim3 grid((Tout + TN - 1) / TN, BATCH);
        wn_hmma<<<grid, 256, SMEM_SZ>>>(
            cur, xo,
            wAf + (size_t)L * 16 * 8 * 32 * 2,
            wRf + (size_t)L *  8 * 8 * 32 * 2,
            wSf + (size_t)L *  8 * 8 * 32 * 2,
            b_res + (size_t)L * C,
            b_skip + (size_t)L * C,
            out + (size_t)L * BATCH * C * SKIP_T,
            dd, Sin, Tout, Sout);
        cur = xo;
        Tin = Tout;
        Sin = Sout;
    }
}

// round 6
// speedup vs baseline: 1.8289x; 1.2252x over previous
#include <cuda_runtime.h>
#include <cuda_bf16.h>
#include <cstdint>

#define NB      40
#define C       128
#define BATCH   4
#define TMAX    8192
#define SKIP_T  4096
#define TN      64

// ======================= device scratch (no allocs allowed) =======================
__device__ float g_x0[BATCH * C * TMAX];
__device__ float g_x1[BATCH * C * TMAX];
// A-operand fragments, packed per-lane in mma register order. Each slot = 2 x uint4 (hi, lo).
__device__ uint4 g_wAf[NB * 16 * 8 * 32 * 2];   // GEMM1: 16 ksteps
__device__ uint4 g_wRf[NB *  8 * 8 * 32 * 2];   // res:   8 ksteps
__device__ uint4 g_wSf[NB *  8 * 8 * 32 * 2];   // skip:  8 ksteps

#define SWZ(o) ((uint32_t)(o) ^ ((((uint32_t)(o)) >> 3) & 0x70u))

__device__ __forceinline__ uint32_t smem_to_u32(const void* p) {
    uint32_t a;
    asm("{ .reg .u64 t; cvta.to.shared.u64 t, %1; cvt.u32.u64 %0, t; }" : "=r"(a) : "l"(p));
    return a;
}

__device__ __forceinline__ void mma_bf16(float* c, const uint32_t* a, const uint32_t* b) {
    asm volatile("mma.sync.aligned.m16n8k16.row.col.f32.bf16.bf16.f32 "
        "{%0,%1,%2,%3}, {%4,%5,%6,%7}, {%8,%9}, {%0,%1,%2,%3};"
        : "+f"(c[0]), "+f"(c[1]), "+f"(c[2]), "+f"(c[3])
        : "r"(a[0]), "r"(a[1]), "r"(a[2]), "r"(a[3]), "r"(b[0]), "r"(b[1]));
}

__device__ __forceinline__ void ldsm_x4(uint32_t* r, uint32_t addr) {
    asm volatile("ldmatrix.sync.aligned.m8n8.x4.shared.b16 {%0,%1,%2,%3}, [%4];"
        : "=r"(r[0]), "=r"(r[1]), "=r"(r[2]), "=r"(r[3]) : "r"(addr));
}

__device__ __forceinline__ uint32_t pk2(float a, float b) {
    __nv_bfloat162 t = __floats2bfloat162_rn(a, b);
    return *reinterpret_cast<uint32_t*>(&t);
}
__device__ __forceinline__ void hilo(float v, float& h, float& l) {
    h = __bfloat162float(__float2bfloat16(v));
    l = v - h;
}

// gate(y) = tanh(y) * sigmoid(y), exp-based (accurate, no NaN at extremes)
__device__ __forceinline__ float gatef(float y) {
    float ay = fabsf(y);
    float e2 = __expf(-2.f * ay);
    float th = (1.f - e2) / (1.f + e2);          // tanh(|y|)
    th = copysignf(th, y);
    float sg = 1.f / (1.f + __expf(-y));
    return th * sg;
}

// ======================= prep: pack A fragments in register order =======================
__global__ void prep_frags(const float* __restrict__ w_dil,
                           const float* __restrict__ w_res,
                           const float* __restrict__ w_skip) {
    int idx = blockIdx.x * blockDim.x + threadIdx.x;
    if (idx < NB * 16 * 8 * 32) {
        int lane = idx & 31, mt = (idx >> 5) & 7, ks = (idx >> 8) & 15, blk = idx >> 12;
        int r = lane >> 2, c2 = (lane & 3) * 2;
        int mr[2] = { mt * 16 + r, mt * 16 + r + 8 };
        int kc[2] = { ks * 16 + c2, ks * 16 + c2 + 8 };
        float h[2][2][2], l[2][2][2];
        #pragma unroll
        for (int mi = 0; mi < 2; mi++)
            #pragma unroll
            for (int kh = 0; kh < 2; kh++)
                #pragma unroll
                for (int e = 0; e < 2; e++) {
                    int k = kc[kh] + e;
                    int tap = k >> 7, ch = k & 127;
                    float v = w_dil[(((size_t)blk * C + mr[mi]) * C + ch) * 2 + tap];
                    hilo(v, h[mi][kh][e], l[mi][kh][e]);
                }
        uint4 hv = { pk2(h[0][0][0], h[0][0][1]), pk2(h[1][0][0], h[1][0][1]),
                     pk2(h[0][1][0], h[0][1][1]), pk2(h[1][1][0], h[1][1][1]) };
        uint4 lv = { pk2(l[0][0][0], l[0][0][1]), pk2(l[1][0][0], l[1][0][1]),
                     pk2(l[0][1][0], l[0][1][1]), pk2(l[1][1][0], l[1][1][1]) };
        g_wAf[(size_t)idx * 2]     = hv;
        g_wAf[(size_t)idx * 2 + 1] = lv;
    }
    if (idx < NB * 8 * 8 * 32) {
        int lane = idx & 31, mt = (idx >> 5) & 7, ks = (idx >> 8) & 7, blk = idx >> 11;
        int r = lane >> 2, c2 = (lane & 3) * 2;
        int mr[2] = { mt * 16 + r, mt * 16 + r + 8 };
        int kc[2] = { ks * 16 + c2, ks * 16 + c2 + 8 };
        float hR[2][2][2], lR[2][2][2], hS[2][2][2], lS[2][2][2];
        #pragma unroll
        for (int mi = 0; mi < 2; mi++)
            #pragma unroll
            for (int kh = 0; kh < 2; kh++)
                #pragma unroll
                for (int e = 0; e < 2; e++) {
                    int k = kc[kh] + e;
                    float vr = w_res [((size_t)blk * C + mr[mi]) * C + k];
                    float vs = w_skip[((size_t)blk * C + mr[mi]) * C + k];
                    hilo(vr, hR[mi][kh][e], lR[mi][kh][e]);
                    hilo(vs, hS[mi][kh][e], lS[mi][kh][e]);
                }
        uint4 v;
        v = make_uint4(pk2(hR[0][0][0],hR[0][0][1]), pk2(hR[1][0][0],hR[1][0][1]),
                       pk2(hR[0][1][0],hR[0][1][1]), pk2(hR[1][1][0],hR[1][1][1]));
        g_wRf[(size_t)idx * 2] = v;
        v = make_uint4(pk2(lR[0][0][0],lR[0][0][1]), pk2(lR[1][0][0],lR[1][0][1]),
                       pk2(lR[0][1][0],lR[0][1][1]), pk2(lR[1][1][0],lR[1][1][1]));
        g_wRf[(size_t)idx * 2 + 1] = v;
        v = make_uint4(pk2(hS[0][0][0],hS[0][0][1]), pk2(hS[1][0][0],hS[1][0][1]),
                       pk2(hS[0][1][0],hS[0][1][1]), pk2(hS[1][1][0],hS[1][1][1]));
        g_wSf[(size_t)idx * 2] = v;
        v = make_uint4(pk2(lS[0][0][0],lS[0][0][1]), pk2(lS[1][0][0],lS[1][0][1]),
                       pk2(lS[0][1][0],lS[0][1][1]), pk2(lS[1][1][0],lS[1][1][1]));
        g_wSf[(size_t)idx * 2 + 1] = v;
    }
}

// ======================= fused block kernel =======================
// smem layout (dynamic, 64KB):
//   B1 hi: [0, 32K)   4 chunks of [64 n rows][64 k cols] bf16, SW128, 8192B each
//   B1 lo: [32K, 64K)
//   G  hi: [0, 16K)   2 chunks (reuses B1 region after phase-1 sync)
//   G  lo: [16K, 32K)
#define SM_B1H 0u
#define SM_B1L 32768u
#define SM_GH  0u
#define SM_GL  16384u
#define SMEM_SZ 65536

struct Frag { uint32_t a[4]; };
__device__ __forceinline__ Frag ldfrag(const uint4* p) {
    uint4 v = __ldg(p);
    Frag f; f.a[0] = v.x; f.a[1] = v.y; f.a[2] = v.z; f.a[3] = v.w;
    return f;
}

__global__ __launch_bounds__(256, 2)
void wn_hmma(const float* __restrict__ xin, float* __restrict__ xout,
             const uint4* __restrict__ Af, const uint4* __restrict__ Rf,
             const uint4* __restrict__ Sf,
             const float* __restrict__ brs, const float* __restrict__ bsk,
             float* __restrict__ skip_out,
             int d, int Sin, int Tout, int Sout)
{
    extern __shared__ __align__(1024) char smem[];
    const uint32_t sbase = smem_to_u32(smem);
    const int tid  = threadIdx.x;
    const int wid  = tid >> 5;
    const int lane = tid & 31;
    const int t0   = blockIdx.x * TN;
    const int b    = blockIdx.y;
    const int mt   = wid;                 // each warp: 16 m-rows x 64 n
    const int m0   = mt * 16;

    const float* xb = xin + (size_t)b * C * Sin;

    // ---------------- stage B1: x taps -> [n][k] bf16 hi/lo, swizzled ----------------
    {
        const int kp = tid & 127;         // k pair index: k = 2kp, 2kp+1
        const int th = tid >> 7;          // t half
        const int k0 = kp * 2;
        const int g  = k0 >> 6;
        const int kc = (k0 & 63) * 2;
        const int off = (k0 >= 128) ? d : 0;
        const int ch0 = k0 & 127, ch1 = (k0 + 1) & 127;
        const float* s0 = xb + (size_t)ch0 * Sin + t0 + off;
        const float* s1 = xb + (size_t)ch1 * Sin + t0 + off;
        const int tr0 = th * 32;
        char* dh = smem + SM_B1H + g * 8192;
        char* dl = smem + SM_B1L + g * 8192;
        bool vec = (t0 + TN <= Tout) && (((t0 + off) & 3) == 0);
        if (vec) {
            #pragma unroll
            for (int q = 0; q < 8; q++) {
                int tt = tr0 + q * 4;
                float4 a = __ldg((const float4*)(s0 + tt));
                float4 bq = __ldg((const float4*)(s1 + tt));
                float av[4] = {a.x, a.y, a.z, a.w};
                float bv[4] = {bq.x, bq.y, bq.z, bq.w};
                #pragma unroll
                for (int j = 0; j < 4; j++) {
                    float ha, la, hb, lb;
                    hilo(av[j], ha, la); hilo(bv[j], hb, lb);
                    uint32_t o = SWZ((tt + j) * 128 + kc);
                    *(uint32_t*)(dh + o) = pk2(ha, hb);
                    *(uint32_t*)(dl + o) = pk2(la, lb);
                }
            }
        } else {
            #pragma unroll 4
            for (int j = 0; j < 32; j++) {
                int tt = tr0 + j;
                float av = (t0 + tt < Tout) ? __ldg(s0 + tt) : 0.f;
                float bv = (t0 + tt < Tout) ? __ldg(s1 + tt) : 0.f;
                float ha, la, hb, lb;
                hilo(av, ha, la); hilo(bv, hb, lb);
                uint32_t o = SWZ(tt * 128 + kc);
                *(uint32_t*)(dh + o) = pk2(ha, hb);
                *(uint32_t*)(dl + o) = pk2(la, lb);
            }
        }
    }
    __syncthreads();

    const int lrow = (((lane >> 4) & 1) << 3) + (lane & 7);
    const int lcol = (lane >> 3) & 1;

    // ---------------- phase 1: Y = W1 @ [x_tap0 ; x_tap1], K=256 ----------------
    float acc1[8][4];
    #pragma unroll
    for (int j = 0; j < 8; j++)
        #pragma unroll
        for (int q = 0; q < 4; q++) acc1[j][q] = 0.f;

    {
        const uint4* fp = Af + ((mt * 32 + lane) << 1);
        Frag aH = ldfrag(fp), aL = ldfrag(fp + 1);
        for (int ks = 0; ks < 16; ks++) {
            Frag nH, nL;
            if (ks < 15) {
                const uint4* np = Af + ((((ks + 1) * 8 + mt) * 32 + lane) << 1);
                nH = ldfrag(np); nL = ldfrag(np + 1);
            }
            const int g = ks >> 2, kk = ks & 3;
            const uint32_t cbh = sbase + SM_B1H + g * 8192;
            const uint32_t cbl = sbase + SM_B1L + g * 8192;
            #pragma unroll
            for (int jp = 0; jp < 4; jp++) {
                uint32_t off = ((jp * 16 + lrow) << 7) + (kk << 5) + (lcol << 4);
                uint32_t bh[4], bl[4];
                ldsm_x4(bh, cbh + SWZ(off));
                ldsm_x4(bl, cbl + SWZ(off));
                mma_bf16(acc1[2*jp],     aH.a, bh);
                mma_bf16(acc1[2*jp + 1], aH.a, bh + 2);
                mma_bf16(acc1[2*jp],     aH.a, bl);
                mma_bf16(acc1[2*jp + 1], aH.a, bl + 2);
                mma_bf16(acc1[2*jp],     aL.a, bh);
                mma_bf16(acc1[2*jp + 1], aL.a, bh + 2);
            }
            aH = nH; aL = nL;
        }
    }
    __syncthreads();   // all warps done reading B1 before G overwrites it

    // ---------------- gate -> G smem [n][k=mid] hi/lo ----------------
    {
        const int r = lane >> 2, c2 = (lane & 3) * 2;
        #pragma unroll
        for (int j = 0; j < 8; j++) {
            #pragma unroll
            for (int q = 0; q < 4; q++) {
                int m = m0 + r + ((q >> 1) << 3);
                int n = j * 8 + c2 + (q & 1);
                float gv = gatef(acc1[j][q]);
                float h, l; hilo(gv, h, l);
                uint32_t o = (uint32_t)(m >> 6) * 8192u + SWZ(n * 128 + (m & 63) * 2);
                *(__nv_bfloat16*)(smem + SM_GH + o) = __float2bfloat16(h);
                *(__nv_bfloat16*)(smem + SM_GL + o) = __float2bfloat16(l);
            }
        }
    }
    __syncthreads();

    const int r_    = lane >> 2;
    const int c2_   = (lane & 3) * 2;
    const int mA    = m0 + r_, mB = mA + 8;
    const int skip_base = Tout - SKIP_T;

    // ---------------- phase 2a: R = Wres @ G  ->  xout ----------------
    {
        float acc[8][4];
        #pragma unroll
        for (int j = 0; j < 8; j++)
            #pragma unroll
            for (int q = 0; q < 4; q++) acc[j][q] = 0.f;

        const uint4* rp = Rf + ((mt * 32 + lane) << 1);
        Frag wH = ldfrag(rp), wL = ldfrag(rp + 1);
        for (int ks = 0; ks < 8; ks++) {
            Frag nH, nL;
            if (ks < 7) {
                const uint4* np = Rf + ((((ks + 1) * 8 + mt) * 32 + lane) << 1);
                nH = ldfrag(np); nL = ldfrag(np + 1);
            }
            const int g = ks >> 2, kk = ks & 3;
            const uint32_t cbh = sbase + SM_GH + g * 8192;
            const uint32_t cbl = sbase + SM_GL + g * 8192;
            #pragma unroll
            for (int jp = 0; jp < 4; jp++) {
                uint32_t off = ((jp * 16 + lrow) << 7) + (kk << 5) + (lcol << 4);
                uint32_t bh[4], bl[4];
                ldsm_x4(bh, cbh + SWZ(off));
                ldsm_x4(bl, cbl + SWZ(off));
                mma_bf16(acc[2*jp],     wH.a, bh);
                mma_bf16(acc[2*jp + 1], wH.a, bh + 2);
                mma_bf16(acc[2*jp],     wH.a, bl);
                mma_bf16(acc[2*jp + 1], wH.a, bl + 2);
                mma_bf16(acc[2*jp],     wL.a, bh);
                mma_bf16(acc[2*jp + 1], wL.a, bh + 2);
            }
            wH = nH; wL = nL;
        }

        const float brA = brs[mA], brB = brs[mB];
        const float* xrA = xb + (size_t)mA * Sin + d;
        const float* xrB = xb + (size_t)mB * Sin + d;
        float* xoA = xout + ((size_t)b * C + mA) * Sout;
        float* xoB = xout + ((size_t)b * C + mB) * Sout;
        #pragma unroll
        for (int j = 0; j < 8; j++) {
            int t = t0 + j * 8 + c2_;
            #pragma unroll
            for (int e = 0; e < 2; e++) {
                int tt = t + e;
                if (tt < Tout) {
                    xoA[tt] = acc[j][e]     + brA + __ldg(xrA + tt);
                    xoB[tt] = acc[j][2 + e] + brB + __ldg(xrB + tt);
                }
            }
        }
    }

    // ---------------- phase 2b: S = Wskip @ G  ->  skip_out ----------------
    {
        float acc[8][4];
        #pragma unroll
        for (int j = 0; j < 8; j++)
            #pragma unroll
            for (int q = 0; q < 4; q++) acc[j][q] = 0.f;

        const uint4* sp = Sf + ((mt * 32 + lane) << 1);
        Frag wH = ldfrag(sp), wL = ldfrag(sp + 1);
        for (int ks = 0; ks < 8; ks++) {
            Frag nH, nL;
            if (ks < 7) {
                const uint4* np = Sf + ((((ks + 1) * 8 + mt) * 32 + lane) << 1);
                nH = ldfrag(np); nL = ldfrag(np + 1);
            }
            const int g = ks >> 2, kk = ks & 3;
            const uint32_t cbh = sbase + SM_GH + g * 8192;
            const uint32_t cbl = sbase + SM_GL + g * 8192;
            #pragma unroll
            for (int jp = 0; jp < 4; jp++) {
                uint32_t off = ((jp * 16 + lrow) << 7) + (kk << 5) + (lcol << 4);
                uint32_t bh[4], bl[4];
                ldsm_x4(bh, cbh + SWZ(off));
                ldsm_x4(bl, cbl + SWZ(off));
                mma_bf16(acc[2*jp],     wH.a, bh);
                mma_bf16(acc[2*jp + 1], wH.a, bh + 2);
                mma_bf16(acc[2*jp],     wH.a, bl);
                mma_bf16(acc[2*jp + 1], wH.a, bl + 2);
                mma_bf16(acc[2*jp],     wL.a, bh);
                mma_bf16(acc[2*jp + 1], wL.a, bh + 2);
            }
            wH = nH; wL = nL;
        }

        const float bsA = bsk[mA], bsB = bsk[mB];
        float* soA = skip_out + ((size_t)b * C + mA) * SKIP_T;
        float* soB = skip_out + ((size_t)b * C + mB) * SKIP_T;
        #pragma unroll
        for (int j = 0; j < 8; j++) {
            int t = t0 + j * 8 + c2_;
            #pragma unroll
            for (int e = 0; e < 2; e++) {
                int tt = t + e;
                if (tt < Tout) {
                    int ts = tt - skip_base;
                    if (ts >= 0) {
                        soA[ts] = acc[j][e]     + bsA;
                        soB[ts] = acc[j][2 + e] + bsB;
                    }
                }
            }
        }
    }
}

// ======================= host =======================
static const int DIL[NB] = {
    1, 2, 4, 8, 16, 32, 64, 128, 256, 512,
    1, 2, 4, 8, 16, 32, 64, 128, 256, 512,
    1, 2, 4, 8, 16, 32, 64, 128, 256, 512,
    1, 2, 4, 8, 16, 32, 64, 128, 256, 512
};

extern "C" void kernel_launch(void* const* d_in, const int* in_sizes, int n_in,
                              void* d_out, int out_size)
{
    const float* x      = (const float*)d_in[0];
    const float* w_dil  = (const float*)d_in[1];
    const float* w_res  = (const float*)d_in[2];
    const float* b_res  = (const float*)d_in[3];
    const float* w_skip = (const float*)d_in[4];
    const float* b_skip = (const float*)d_in[5];
    float* out = (float*)d_out;

    float *xb0, *xb1;
    uint4 *wAf, *wRf, *wSf;
    cudaGetSymbolAddress((void**)&xb0, g_x0);
    cudaGetSymbolAddress((void**)&xb1, g_x1);
    cudaGetSymbolAddress((void**)&wAf, g_wAf);
    cudaGetSymbolAddress((void**)&wRf, g_wRf);
    cudaGetSymbolAddress((void**)&wSf, g_wSf);

    cudaFuncSetAttribute(wn_hmma, cudaFuncAttributeMaxDynamicSharedMemorySize, SMEM_SZ);

    {
        int total = NB * 16 * 8 * 32;
        prep_frags<<<(total + 255) / 256, 256>>>(w_dil, w_res, w_skip);
    }

    int Tin = TMAX;
    int Sin = TMAX;
    const float* cur = x;
    for (int L = 0; L < NB; L++) {
        int dd   = DIL[L];
        int Tout = Tin - dd;
        int Sout = (Tout + 3) & ~3;
        float* xo = (L & 1) ? xb1 : xb0;
        dim3 grid((Tout + TN - 1) / TN, BATCH);
        wn_hmma<<<grid, 256, SMEM_SZ>>>(
            cur, xo,
            wAf + (size_t)L * 16 * 8 * 32 * 2,
            wRf + (size_t)L *  8 * 8 * 32 * 2,
            wSf + (size_t)L *  8 * 8 * 32 * 2,
            b_res + (size_t)L * C,
            b_skip + (size_t)L * C,
            out + (size_t)L * BATCH * C * SKIP_T,
            dd, Sin, Tout, Sout);
        cur = xo;
        Tin = Tout;
        Sin = Sout;
    }
}

// round 7
// speedup vs baseline: 2.2989x; 1.2570x over previous
#include <cuda_runtime.h>
#include <cuda_bf16.h>
#include <cstdint>

#define NB      40
#define C       128
#define BATCH   4
#define TMAX    8192
#define SKIP_T  4096
#define TN      64

// ======================= device scratch (no allocs allowed) =======================
// residual stream, time-major: [b][t][c]
__device__ float g_x0[BATCH * TMAX * C];
__device__ float g_x1[BATCH * TMAX * C];
// A-operand fragments, packed per-lane in mma register order. Each slot = 2 x uint4 (hi, lo).
__device__ uint4 g_wAf[NB * 16 * 8 * 32 * 2];   // GEMM1: 16 ksteps
__device__ uint4 g_wRf[NB *  8 * 8 * 32 * 2];   // res:   8 ksteps
__device__ uint4 g_wSf[NB *  8 * 8 * 32 * 2];   // skip:  8 ksteps

#define SWZ(o) ((uint32_t)(o) ^ ((((uint32_t)(o)) >> 3) & 0x70u))

__device__ __forceinline__ uint32_t smem_to_u32(const void* p) {
    uint32_t a;
    asm("{ .reg .u64 t; cvta.to.shared.u64 t, %1; cvt.u32.u64 %0, t; }" : "=r"(a) : "l"(p));
    return a;
}

__device__ __forceinline__ void mma_bf16(float* c, const uint32_t* a, const uint32_t* b) {
    asm volatile("mma.sync.aligned.m16n8k16.row.col.f32.bf16.bf16.f32 "
        "{%0,%1,%2,%3}, {%4,%5,%6,%7}, {%8,%9}, {%0,%1,%2,%3};"
        : "+f"(c[0]), "+f"(c[1]), "+f"(c[2]), "+f"(c[3])
        : "r"(a[0]), "r"(a[1]), "r"(a[2]), "r"(a[3]), "r"(b[0]), "r"(b[1]));
}

__device__ __forceinline__ void ldsm_x4(uint32_t* r, uint32_t addr) {
    asm volatile("ldmatrix.sync.aligned.m8n8.x4.shared.b16 {%0,%1,%2,%3}, [%4];"
        : "=r"(r[0]), "=r"(r[1]), "=r"(r[2]), "=r"(r[3]) : "r"(addr));
}

__device__ __forceinline__ uint32_t pk2(float a, float b) {
    __nv_bfloat162 t = __floats2bfloat162_rn(a, b);
    return *reinterpret_cast<uint32_t*>(&t);
}
__device__ __forceinline__ void hilo(float v, float& h, float& l) {
    h = __bfloat162float(__float2bfloat16(v));
    l = v - h;
}

// gate(y) = tanh(y)*sigmoid(y) = (1-u)/(1+u^2), u = e^{-y}  (exact identity)
__device__ __forceinline__ float gatef(float y) {
    float u = __expf(-fmaxf(y, -15.f));
    return __fdividef(1.f - u, 1.f + u * u);
}

// ======================= transpose input [b][c][t] -> scratch [b][t][c] =======================
__global__ void transpose_in(const float* __restrict__ x, float* __restrict__ xt) {
    __shared__ float tile[32][33];
    const int b  = blockIdx.z;
    const int c0 = blockIdx.y * 32;
    const int tb = blockIdx.x * 32;
    const int tx = threadIdx.x, ty = threadIdx.y;
    #pragma unroll
    for (int i = 0; i < 32; i += 8)
        tile[ty + i][tx] = x[((size_t)b * C + c0 + ty + i) * TMAX + tb + tx];
    __syncthreads();
    #pragma unroll
    for (int i = 0; i < 32; i += 8)
        xt[((size_t)b * TMAX + tb + ty + i) * C + c0 + tx] = tile[tx][ty + i];
}

// ======================= prep: pack A fragments in register order =======================
__global__ void prep_frags(const float* __restrict__ w_dil,
                           const float* __restrict__ w_res,
                           const float* __restrict__ w_skip) {
    int idx = blockIdx.x * blockDim.x + threadIdx.x;
    if (idx < NB * 16 * 8 * 32) {
        int lane = idx & 31, mt = (idx >> 5) & 7, ks = (idx >> 8) & 15, blk = idx >> 12;
        int r = lane >> 2, c2 = (lane & 3) * 2;
        int mr[2] = { mt * 16 + r, mt * 16 + r + 8 };
        int kc[2] = { ks * 16 + c2, ks * 16 + c2 + 8 };
        float h[2][2][2], l[2][2][2];
        #pragma unroll
        for (int mi = 0; mi < 2; mi++)
            #pragma unroll
            for (int kh = 0; kh < 2; kh++)
                #pragma unroll
                for (int e = 0; e < 2; e++) {
                    int k = kc[kh] + e;
                    int tap = k >> 7, ch = k & 127;
                    float v = w_dil[(((size_t)blk * C + mr[mi]) * C + ch) * 2 + tap];
                    hilo(v, h[mi][kh][e], l[mi][kh][e]);
                }
        uint4 hv = { pk2(h[0][0][0], h[0][0][1]), pk2(h[1][0][0], h[1][0][1]),
                     pk2(h[0][1][0], h[0][1][1]), pk2(h[1][1][0], h[1][1][1]) };
        uint4 lv = { pk2(l[0][0][0], l[0][0][1]), pk2(l[1][0][0], l[1][0][1]),
                     pk2(l[0][1][0], l[0][1][1]), pk2(l[1][1][0], l[1][1][1]) };
        g_wAf[(size_t)idx * 2]     = hv;
        g_wAf[(size_t)idx * 2 + 1] = lv;
    }
    if (idx < NB * 8 * 8 * 32) {
        int lane = idx & 31, mt = (idx >> 5) & 7, ks = (idx >> 8) & 7, blk = idx >> 11;
        int r = lane >> 2, c2 = (lane & 3) * 2;
        int mr[2] = { mt * 16 + r, mt * 16 + r + 8 };
        int kc[2] = { ks * 16 + c2, ks * 16 + c2 + 8 };
        float hR[2][2][2], lR[2][2][2], hS[2][2][2], lS[2][2][2];
        #pragma unroll
        for (int mi = 0; mi < 2; mi++)
            #pragma unroll
            for (int kh = 0; kh < 2; kh++)
                #pragma unroll
                for (int e = 0; e < 2; e++) {
                    int k = kc[kh] + e;
                    float vr = w_res [((size_t)blk * C + mr[mi]) * C + k];
                    float vs = w_skip[((size_t)blk * C + mr[mi]) * C + k];
                    hilo(vr, hR[mi][kh][e], lR[mi][kh][e]);
                    hilo(vs, hS[mi][kh][e], lS[mi][kh][e]);
                }
        uint4 v;
        v = make_uint4(pk2(hR[0][0][0],hR[0][0][1]), pk2(hR[1][0][0],hR[1][0][1]),
                       pk2(hR[0][1][0],hR[0][1][1]), pk2(hR[1][1][0],hR[1][1][1]));
        g_wRf[(size_t)idx * 2] = v;
        v = make_uint4(pk2(lR[0][0][0],lR[0][0][1]), pk2(lR[1][0][0],lR[1][0][1]),
                       pk2(lR[0][1][0],lR[0][1][1]), pk2(lR[1][1][0],lR[1][1][1]));
        g_wRf[(size_t)idx * 2 + 1] = v;
        v = make_uint4(pk2(hS[0][0][0],hS[0][0][1]), pk2(hS[1][0][0],hS[1][0][1]),
                       pk2(hS[0][1][0],hS[0][1][1]), pk2(hS[1][1][0],hS[1][1][1]));
        g_wSf[(size_t)idx * 2] = v;
        v = make_uint4(pk2(lS[0][0][0],lS[0][0][1]), pk2(lS[1][0][0],lS[1][0][1]),
                       pk2(lS[0][1][0],lS[0][1][1]), pk2(lS[1][1][0],lS[1][1][1]));
        g_wSf[(size_t)idx * 2 + 1] = v;
    }
}

// ======================= fused block kernel =======================
// smem layout (dynamic, 96KB): B1 hi [0,32K), B1 lo [32K,64K), G hi [64K,80K), G lo [80K,96K)
#define SM_B1H 0u
#define SM_B1L 32768u
#define SM_GH  65536u
#define SM_GL  81920u
#define SMEM_SZ 98304

struct Frag { uint32_t a[4]; };
__device__ __forceinline__ Frag ldfrag(const uint4* p) {
    uint4 v = __ldg(p);
    Frag f; f.a[0] = v.x; f.a[1] = v.y; f.a[2] = v.z; f.a[3] = v.w;
    return f;
}

__global__ __launch_bounds__(256, 2)
void wn_hmma(const float* __restrict__ xin, float* __restrict__ xout,
             const uint4* __restrict__ Af, const uint4* __restrict__ Rf,
             const uint4* __restrict__ Sf,
             const float* __restrict__ brs, const float* __restrict__ bsk,
             float* __restrict__ skip_out,
             int d, int Tin, int Tout)
{
    extern __shared__ __align__(1024) char smem[];
    const uint32_t sbase = smem_to_u32(smem);
    const int tid  = threadIdx.x;
    const int wid  = tid >> 5;
    const int lane = tid & 31;
    const int t0   = blockIdx.x * TN;
    const int b    = blockIdx.y;
    const int mt   = wid;                 // each warp: 16 m-rows x 64 n
    const int m0   = mt * 16;

    const float* xbt = xin + (size_t)b * TMAX * C;   // [t][c]

    // ---------------- stage B1: coalesced row loads, [t 64][k 256] bf16 hi/lo ----------------
    {
        #pragma unroll
        for (int it = 0; it < 16; it++) {
            int job = wid * 16 + it;      // 0..127
            int tap = job >> 6, row = job & 63;
            int tabs = t0 + row + (tap ? d : 0);
            if (tabs >= Tin) tabs = Tin - 1;   // clamp: out-of-range columns are discarded later
            float4 v = __ldg((const float4*)(xbt + (size_t)tabs * C) + lane);
            float h0, l0, h1, l1, h2, l2, h3, l3;
            hilo(v.x, h0, l0); hilo(v.y, h1, l1); hilo(v.z, h2, l2); hilo(v.w, h3, l3);
            uint32_t o = (uint32_t)(tap * 2 + (lane >> 4)) * 8192u
                       + SWZ(row * 128 + (lane & 15) * 8);
            *(uint2*)(smem + SM_B1H + o) = make_uint2(pk2(h0, h1), pk2(h2, h3));
            *(uint2*)(smem + SM_B1L + o) = make_uint2(pk2(l0, l1), pk2(l2, l3));
        }
    }
    __syncthreads();

    const int lrow = (((lane >> 4) & 1) << 3) + (lane & 7);
    const int lcol = (lane >> 3) & 1;

    // ---------------- phase 1: Y = W1 @ [x_tap0 ; x_tap1], K=256 ----------------
    float acc1[8][4];
    #pragma unroll
    for (int j = 0; j < 8; j++)
        #pragma unroll
        for (int q = 0; q < 4; q++) acc1[j][q] = 0.f;

    {
        const uint4* fp = Af + ((mt * 32 + lane) << 1);
        Frag aH = ldfrag(fp), aL = ldfrag(fp + 1);
        for (int ks = 0; ks < 16; ks++) {
            Frag nH, nL;
            if (ks < 15) {
                const uint4* np = Af + ((((ks + 1) * 8 + mt) * 32 + lane) << 1);
                nH = ldfrag(np); nL = ldfrag(np + 1);
            }
            const int g = ks >> 2, kk = ks & 3;
            const uint32_t cbh = sbase + SM_B1H + g * 8192;
            const uint32_t cbl = sbase + SM_B1L + g * 8192;
            #pragma unroll
            for (int jp = 0; jp < 4; jp++) {
                uint32_t off = ((jp * 16 + lrow) << 7) + (kk << 5) + (lcol << 4);
                uint32_t bh[4], bl[4];
                ldsm_x4(bh, cbh + SWZ(off));
                ldsm_x4(bl, cbl + SWZ(off));
                mma_bf16(acc1[2*jp],     aH.a, bh);
                mma_bf16(acc1[2*jp + 1], aH.a, bh + 2);
                mma_bf16(acc1[2*jp],     aH.a, bl);
                mma_bf16(acc1[2*jp + 1], aH.a, bl + 2);
                mma_bf16(acc1[2*jp],     aL.a, bh);
                mma_bf16(acc1[2*jp + 1], aL.a, bh + 2);
            }
            aH = nH; aL = nL;
        }
    }
    // NOTE: no barrier here — G lives in its own smem region, B1 is not overwritten.

    // ---------------- gate -> G smem [n][k=mid] hi/lo ----------------
    {
        const int r = lane >> 2, c2 = (lane & 3) * 2;
        #pragma unroll
        for (int j = 0; j < 8; j++) {
            #pragma unroll
            for (int q = 0; q < 4; q++) {
                int m = m0 + r + ((q >> 1) << 3);
                int n = j * 8 + c2 + (q & 1);
                float gv = gatef(acc1[j][q]);
                float h, l; hilo(gv, h, l);
                uint32_t o = (uint32_t)(m >> 6) * 8192u + SWZ(n * 128 + (m & 63) * 2);
                *(__nv_bfloat16*)(smem + SM_GH + o) = __float2bfloat16(h);
                *(__nv_bfloat16*)(smem + SM_GL + o) = __float2bfloat16(l);
            }
        }
    }
    __syncthreads();

    const int r_    = lane >> 2;
    const int c2_   = (lane & 3) * 2;
    const int mA    = m0 + r_, mB = mA + 8;
    const int skip_base = Tout - SKIP_T;
    float* xbo = xout + (size_t)b * TMAX * C;   // [t][c]

    // ---------------- phase 2a: R = Wres @ G  ->  xout ----------------
    {
        float acc[8][4];
        #pragma unroll
        for (int j = 0; j < 8; j++)
            #pragma unroll
            for (int q = 0; q < 4; q++) acc[j][q] = 0.f;

        const uint4* rp = Rf + ((mt * 32 + lane) << 1);
        Frag wH = ldfrag(rp), wL = ldfrag(rp + 1);
        for (int ks = 0; ks < 8; ks++) {
            Frag nH, nL;
            if (ks < 7) {
                const uint4* np = Rf + ((((ks + 1) * 8 + mt) * 32 + lane) << 1);
                nH = ldfrag(np); nL = ldfrag(np + 1);
            }
            const int g = ks >> 2, kk = ks & 3;
            const uint32_t cbh = sbase + SM_GH + g * 8192;
            const uint32_t cbl = sbase + SM_GL + g * 8192;
            #pragma unroll
            for (int jp = 0; jp < 4; jp++) {
                uint32_t off = ((jp * 16 + lrow) << 7) + (kk << 5) + (lcol << 4);
                uint32_t bh[4], bl[4];
                ldsm_x4(bh, cbh + SWZ(off));
                ldsm_x4(bl, cbl + SWZ(off));
                mma_bf16(acc[2*jp],     wH.a, bh);
                mma_bf16(acc[2*jp + 1], wH.a, bh + 2);
                mma_bf16(acc[2*jp],     wH.a, bl);
                mma_bf16(acc[2*jp + 1], wH.a, bl + 2);
                mma_bf16(acc[2*jp],     wL.a, bh);
                mma_bf16(acc[2*jp + 1], wL.a, bh + 2);
            }
            wH = nH; wL = nL;
        }

        const float brA = brs[mA], brB = brs[mB];
        #pragma unroll
        for (int j = 0; j < 8; j++) {
            int t = t0 + j * 8 + c2_;
            #pragma unroll
            for (int e = 0; e < 2; e++) {
                int tt = t + e;
                if (tt < Tout) {
                    const float* xr = xbt + (size_t)(tt + d) * C;
                    float* xo = xbo + (size_t)tt * C;
                    xo[mA] = acc[j][e]     + brA + __ldg(xr + mA);
                    xo[mB] = acc[j][2 + e] + brB + __ldg(xr + mB);
                }
            }
        }
    }

    // ---------------- phase 2b: S = Wskip @ G  ->  skip_out ----------------
    {
        float acc[8][4];
        #pragma unroll
        for (int j = 0; j < 8; j++)
            #pragma unroll
            for (int q = 0; q < 4; q++) acc[j][q] = 0.f;

        const uint4* sp = Sf + ((mt * 32 + lane) << 1);
        Frag wH = ldfrag(sp), wL = ldfrag(sp + 1);
        for (int ks = 0; ks < 8; ks++) {
            Frag nH, nL;
            if (ks < 7) {
                const uint4* np = Sf + ((((ks + 1) * 8 + mt) * 32 + lane) << 1);
                nH = ldfrag(np); nL = ldfrag(np + 1);
            }
            const int g = ks >> 2, kk = ks & 3;
            const uint32_t cbh = sbase + SM_GH + g * 8192;
            const uint32_t cbl = sbase + SM_GL + g * 8192;
            #pragma unroll
            for (int jp = 0; jp < 4; jp++) {
                uint32_t off = ((jp * 16 + lrow) << 7) + (kk << 5) + (lcol << 4);
                uint32_t bh[4], bl[4];
                ldsm_x4(bh, cbh + SWZ(off));
                ldsm_x4(bl, cbl + SWZ(off));
                mma_bf16(acc[2*jp],     wH.a, bh);
                mma_bf16(acc[2*jp + 1], wH.a, bh + 2);
                mma_bf16(acc[2*jp],     wH.a, bl);
                mma_bf16(acc[2*jp + 1], wH.a, bl + 2);
                mma_bf16(acc[2*jp],     wL.a, bh);
                mma_bf16(acc[2*jp + 1], wL.a, bh + 2);
            }
            wH = nH; wL = nL;
        }

        const float bsA = bsk[mA], bsB = bsk[mB];
        float* soA = skip_out + ((size_t)b * C + mA) * SKIP_T;
        float* soB = skip_out + ((size_t)b * C + mB) * SKIP_T;
        #pragma unroll
        for (int j = 0; j < 8; j++) {
            int t = t0 + j * 8 + c2_;
            #pragma unroll
            for (int e = 0; e < 2; e++) {
                int tt = t + e;
                if (tt < Tout) {
                    int ts = tt - skip_base;
                    if (ts >= 0) {
                        soA[ts] = acc[j][e]     + bsA;
                        soB[ts] = acc[j][2 + e] + bsB;
                    }
                }
            }
        }
    }
}

// ======================= host =======================
static const int DIL[NB] = {
    1, 2, 4, 8, 16, 32, 64, 128, 256, 512,
    1, 2, 4, 8, 16, 32, 64, 128, 256, 512,
    1, 2, 4, 8, 16, 32, 64, 128, 256, 512,
    1, 2, 4, 8, 16, 32, 64, 128, 256, 512
};

extern "C" void kernel_launch(void* const* d_in, const int* in_sizes, int n_in,
                              void* d_out, int out_size)
{
    const float* x      = (const float*)d_in[0];
    const float* w_dil  = (const float*)d_in[1];
    const float* w_res  = (const float*)d_in[2];
    const float* b_res  = (const float*)d_in[3];
    const float* w_skip = (const float*)d_in[4];
    const float* b_skip = (const float*)d_in[5];
    float* out = (float*)d_out;

    float *xb0, *xb1;
    uint4 *wAf, *wRf, *wSf;
    cudaGetSymbolAddress((void**)&xb0, g_x0);
    cudaGetSymbolAddress((void**)&xb1, g_x1);
    cudaGetSymbolAddress((void**)&wAf, g_wAf);
    cudaGetSymbolAddress((void**)&wRf, g_wRf);
    cudaGetSymbolAddress((void**)&wSf, g_wSf);

    cudaFuncSetAttribute(wn_hmma, cudaFuncAttributeMaxDynamicSharedMemorySize, SMEM_SZ);

    {
        int total = NB * 16 * 8 * 32;
        prep_frags<<<(total + 255) / 256, 256>>>(w_dil, w_res, w_skip);
    }
    {
        dim3 g(TMAX / 32, C / 32, BATCH);
        transpose_in<<<g, dim3(32, 8)>>>(x, xb0);
    }

    int Tin = TMAX;
    const float* cur = xb0;
    for (int L = 0; L < NB; L++) {
        int dd   = DIL[L];
        int Tout = Tin - dd;
        float* xo = (L & 1) ? xb0 : xb1;
        dim3 grid((Tout + TN - 1) / TN, BATCH);
        wn_hmma<<<grid, 256, SMEM_SZ>>>(
            cur, xo,
            wAf + (size_t)L * 16 * 8 * 32 * 2,
            wRf + (size_t)L *  8 * 8 * 32 * 2,
            wSf + (size_t)L *  8 * 8 * 32 * 2,
            b_res + (size_t)L * C,
            b_skip + (size_t)L * C,
            out + (size_t)L * BATCH * C * SKIP_T,
            dd, Tin, Tout);
        cur = xo;
        Tin = Tout;
    }
}

// round 8
// speedup vs baseline: 2.3442x; 1.0197x over previous
#include <cuda_runtime.h>
#include <cuda_bf16.h>
#include <cstdint>

#define NB      40
#define C       128
#define BATCH   4
#define TMAX    8192
#define SKIP_T  4096
#define TN      64

// ======================= device scratch (no allocs allowed) =======================
// residual stream, time-major: [b][t][c]
__device__ float g_x0[BATCH * TMAX * C];
__device__ float g_x1[BATCH * TMAX * C];
// A-operand fragments, packed per-lane in mma register order. Each slot = 2 x uint4 (hi, lo).
__device__ uint4 g_wAf[NB * 16 * 8 * 32 * 2];   // GEMM1: 16 ksteps
__device__ uint4 g_wRf[NB *  8 * 8 * 32 * 2];   // res:   8 ksteps
__device__ uint4 g_wSf[NB *  8 * 8 * 32 * 2];   // skip:  8 ksteps

#define SWZ(o) ((uint32_t)(o) ^ ((((uint32_t)(o)) >> 3) & 0x70u))

__device__ __forceinline__ uint32_t smem_to_u32(const void* p) {
    uint32_t a;
    asm("{ .reg .u64 t; cvta.to.shared.u64 t, %1; cvt.u32.u64 %0, t; }" : "=r"(a) : "l"(p));
    return a;
}

__device__ __forceinline__ void mma_bf16(float* c, const uint32_t* a, const uint32_t* b) {
    asm volatile("mma.sync.aligned.m16n8k16.row.col.f32.bf16.bf16.f32 "
        "{%0,%1,%2,%3}, {%4,%5,%6,%7}, {%8,%9}, {%0,%1,%2,%3};"
        : "+f"(c[0]), "+f"(c[1]), "+f"(c[2]), "+f"(c[3])
        : "r"(a[0]), "r"(a[1]), "r"(a[2]), "r"(a[3]), "r"(b[0]), "r"(b[1]));
}

__device__ __forceinline__ void ldsm_x4(uint32_t* r, uint32_t addr) {
    asm volatile("ldmatrix.sync.aligned.m8n8.x4.shared.b16 {%0,%1,%2,%3}, [%4];"
        : "=r"(r[0]), "=r"(r[1]), "=r"(r[2]), "=r"(r[3]) : "r"(addr));
}

__device__ __forceinline__ uint32_t pk2(float a, float b) {
    __nv_bfloat162 t = __floats2bfloat162_rn(a, b);
    return *reinterpret_cast<uint32_t*>(&t);
}
__device__ __forceinline__ void hilo(float v, float& h, float& l) {
    h = __bfloat162float(__float2bfloat16(v));
    l = v - h;
}

// gate(y) = tanh(y)*sigmoid(y) = (1-u)/(1+u^2), u = e^{-y}  (exact identity)
__device__ __forceinline__ float gatef(float y) {
    float u = __expf(-fmaxf(y, -15.f));
    return __fdividef(1.f - u, 1.f + u * u);
}

// ======================= transpose input [b][c][t] -> scratch [b][t][c] =======================
__global__ void transpose_in(const float* __restrict__ x, float* __restrict__ xt) {
    __shared__ float tile[32][33];
    const int b  = blockIdx.z;
    const int c0 = blockIdx.y * 32;
    const int tb = blockIdx.x * 32;
    const int tx = threadIdx.x, ty = threadIdx.y;
    #pragma unroll
    for (int i = 0; i < 32; i += 8)
        tile[ty + i][tx] = x[((size_t)b * C + c0 + ty + i) * TMAX + tb + tx];
    __syncthreads();
    #pragma unroll
    for (int i = 0; i < 32; i += 8)
        xt[((size_t)b * TMAX + tb + ty + i) * C + c0 + tx] = tile[tx][ty + i];
}

// ======================= prep: pack A fragments in register order =======================
__global__ void prep_frags(const float* __restrict__ w_dil,
                           const float* __restrict__ w_res,
                           const float* __restrict__ w_skip) {
    int idx = blockIdx.x * blockDim.x + threadIdx.x;
    if (idx < NB * 16 * 8 * 32) {
        int lane = idx & 31, mt = (idx >> 5) & 7, ks = (idx >> 8) & 15, blk = idx >> 12;
        int r = lane >> 2, c2 = (lane & 3) * 2;
        int mr[2] = { mt * 16 + r, mt * 16 + r + 8 };
        int kc[2] = { ks * 16 + c2, ks * 16 + c2 + 8 };
        float h[2][2][2], l[2][2][2];
        #pragma unroll
        for (int mi = 0; mi < 2; mi++)
            #pragma unroll
            for (int kh = 0; kh < 2; kh++)
                #pragma unroll
                for (int e = 0; e < 2; e++) {
                    int k = kc[kh] + e;
                    int tap = k >> 7, ch = k & 127;
                    float v = w_dil[(((size_t)blk * C + mr[mi]) * C + ch) * 2 + tap];
                    hilo(v, h[mi][kh][e], l[mi][kh][e]);
                }
        uint4 hv = { pk2(h[0][0][0], h[0][0][1]), pk2(h[1][0][0], h[1][0][1]),
                     pk2(h[0][1][0], h[0][1][1]), pk2(h[1][1][0], h[1][1][1]) };
        uint4 lv = { pk2(l[0][0][0], l[0][0][1]), pk2(l[1][0][0], l[1][0][1]),
                     pk2(l[0][1][0], l[0][1][1]), pk2(l[1][1][0], l[1][1][1]) };
        g_wAf[(size_t)idx * 2]     = hv;
        g_wAf[(size_t)idx * 2 + 1] = lv;
    }
    if (idx < NB * 8 * 8 * 32) {
        int lane = idx & 31, mt = (idx >> 5) & 7, ks = (idx >> 8) & 7, blk = idx >> 11;
        int r = lane >> 2, c2 = (lane & 3) * 2;
        int mr[2] = { mt * 16 + r, mt * 16 + r + 8 };
        int kc[2] = { ks * 16 + c2, ks * 16 + c2 + 8 };
        float hR[2][2][2], lR[2][2][2], hS[2][2][2], lS[2][2][2];
        #pragma unroll
        for (int mi = 0; mi < 2; mi++)
            #pragma unroll
            for (int kh = 0; kh < 2; kh++)
                #pragma unroll
                for (int e = 0; e < 2; e++) {
                    int k = kc[kh] + e;
                    float vr = w_res [((size_t)blk * C + mr[mi]) * C + k];
                    float vs = w_skip[((size_t)blk * C + mr[mi]) * C + k];
                    hilo(vr, hR[mi][kh][e], lR[mi][kh][e]);
                    hilo(vs, hS[mi][kh][e], lS[mi][kh][e]);
                }
        uint4 v;
        v = make_uint4(pk2(hR[0][0][0],hR[0][0][1]), pk2(hR[1][0][0],hR[1][0][1]),
                       pk2(hR[0][1][0],hR[0][1][1]), pk2(hR[1][1][0],hR[1][1][1]));
        g_wRf[(size_t)idx * 2] = v;
        v = make_uint4(pk2(lR[0][0][0],lR[0][0][1]), pk2(lR[1][0][0],lR[1][0][1]),
                       pk2(lR[0][1][0],lR[0][1][1]), pk2(lR[1][1][0],lR[1][1][1]));
        g_wRf[(size_t)idx * 2 + 1] = v;
        v = make_uint4(pk2(hS[0][0][0],hS[0][0][1]), pk2(hS[1][0][0],hS[1][0][1]),
                       pk2(hS[0][1][0],hS[0][1][1]), pk2(hS[1][1][0],hS[1][1][1]));
        g_wSf[(size_t)idx * 2] = v;
        v = make_uint4(pk2(lS[0][0][0],lS[0][0][1]), pk2(lS[1][0][0],lS[1][0][1]),
                       pk2(lS[0][1][0],lS[0][1][1]), pk2(lS[1][1][0],lS[1][1][1]));
        g_wSf[(size_t)idx * 2 + 1] = v;
    }
}

// ======================= fused block kernel =======================
// smem (dynamic, 97KB + 1KB bias):
//   phase A: B1 hi [0,32K), B1 lo [32K,64K), G hi [64K,80K), G lo [80K,96K)
//   phase B (after barriers): accR [0, 33792) as [t][132] f32;
//                             accS [33792, 68608) as [m][68] f32 (overlaps dead G-hi tail)
//   bias stash: [99328-1024, 99328)
#define SM_B1H  0u
#define SM_B1L  32768u
#define SM_GH   65536u
#define SM_GL   81920u
#define SM_ACCR 0u
#define SM_ACCS 33792u
#define SM_BIAS 98304u
#define SMEM_SZ 99328

struct Frag { uint32_t a[4]; };
__device__ __forceinline__ Frag ldfrag(const uint4* p) {
    uint4 v = __ldg(p);
    Frag f; f.a[0] = v.x; f.a[1] = v.y; f.a[2] = v.z; f.a[3] = v.w;
    return f;
}

__global__ __launch_bounds__(256, 2)
void wn_hmma(const float* __restrict__ xin, float* __restrict__ xout,
             const uint4* __restrict__ Af, const uint4* __restrict__ Rf,
             const uint4* __restrict__ Sf,
             const float* __restrict__ brs, const float* __restrict__ bsk,
             float* __restrict__ skip_out,
             int d, int Tin, int Tout)
{
    extern __shared__ __align__(1024) char smem[];
    const uint32_t sbase = smem_to_u32(smem);
    const int tid  = threadIdx.x;
    const int wid  = tid >> 5;
    const int lane = tid & 31;
    const int t0   = blockIdx.x * TN;
    const int b    = blockIdx.y;
    const int mt   = wid;                 // each warp: 16 m-rows x 64 n
    const int m0   = mt * 16;

    const float* xbt = xin + (size_t)b * TMAX * C;   // [t][c]

    // ---------------- stage biases + B1 (coalesced row loads) ----------------
    if (tid < 128) {
        ((float*)(smem + SM_BIAS))[tid]       = __ldg(brs + tid);
        ((float*)(smem + SM_BIAS + 512))[tid] = __ldg(bsk + tid);
    }
    {
        #pragma unroll
        for (int it = 0; it < 16; it++) {
            int job = wid * 16 + it;      // 0..127
            int tap = job >> 6, row = job & 63;
            int tabs = t0 + row + (tap ? d : 0);
            if (tabs >= Tin) tabs = Tin - 1;   // clamp: out-of-range columns discarded later
            float4 v = __ldg((const float4*)(xbt + (size_t)tabs * C) + lane);
            float h0, l0, h1, l1, h2, l2, h3, l3;
            hilo(v.x, h0, l0); hilo(v.y, h1, l1); hilo(v.z, h2, l2); hilo(v.w, h3, l3);
            uint32_t o = (uint32_t)(tap * 2 + (lane >> 4)) * 8192u
                       + SWZ(row * 128 + (lane & 15) * 8);
            *(uint2*)(smem + SM_B1H + o) = make_uint2(pk2(h0, h1), pk2(h2, h3));
            *(uint2*)(smem + SM_B1L + o) = make_uint2(pk2(l0, l1), pk2(l2, l3));
        }
    }
    __syncthreads();

    const int lrow = (((lane >> 4) & 1) << 3) + (lane & 7);
    const int lcol = (lane >> 3) & 1;

    // ---------------- phase 1: Y = W1 @ [x_tap0 ; x_tap1], K=256 ----------------
    float acc1[8][4];
    #pragma unroll
    for (int j = 0; j < 8; j++)
        #pragma unroll
        for (int q = 0; q < 4; q++) acc1[j][q] = 0.f;

    {
        const uint4* fp = Af + ((mt * 32 + lane) << 1);
        Frag aH = ldfrag(fp), aL = ldfrag(fp + 1);
        for (int ks = 0; ks < 16; ks++) {
            Frag nH, nL;
            if (ks < 15) {
                const uint4* np = Af + ((((ks + 1) * 8 + mt) * 32 + lane) << 1);
                nH = ldfrag(np); nL = ldfrag(np + 1);
            }
            const int g = ks >> 2, kk = ks & 3;
            const uint32_t cbh = sbase + SM_B1H + g * 8192;
            const uint32_t cbl = sbase + SM_B1L + g * 8192;
            #pragma unroll
            for (int jp = 0; jp < 4; jp++) {
                uint32_t off = ((jp * 16 + lrow) << 7) + (kk << 5) + (lcol << 4);
                uint32_t bh[4], bl[4];
                ldsm_x4(bh, cbh + SWZ(off));
                ldsm_x4(bl, cbl + SWZ(off));
                mma_bf16(acc1[2*jp],     aH.a, bh);
                mma_bf16(acc1[2*jp + 1], aH.a, bh + 2);
                mma_bf16(acc1[2*jp],     aH.a, bl);
                mma_bf16(acc1[2*jp + 1], aH.a, bl + 2);
                mma_bf16(acc1[2*jp],     aL.a, bh);
                mma_bf16(acc1[2*jp + 1], aL.a, bh + 2);
            }
            aH = nH; aL = nL;
        }
    }

    // ---------------- gate -> G smem [n][k=mid] hi/lo ----------------
    {
        const int r = lane >> 2, c2 = (lane & 3) * 2;
        #pragma unroll
        for (int j = 0; j < 8; j++) {
            #pragma unroll
            for (int q = 0; q < 4; q++) {
                int m = m0 + r + ((q >> 1) << 3);
                int n = j * 8 + c2 + (q & 1);
                float gv = gatef(acc1[j][q]);
                float h, l; hilo(gv, h, l);
                uint32_t o = (uint32_t)(m >> 6) * 8192u + SWZ(n * 128 + (m & 63) * 2);
                *(__nv_bfloat16*)(smem + SM_GH + o) = __float2bfloat16(h);
                *(__nv_bfloat16*)(smem + SM_GL + o) = __float2bfloat16(l);
            }
        }
    }
    __syncthreads();   // G ready; everyone done with B1 -> B1 region reusable

    const int r_  = lane >> 2;
    const int c2_ = (lane & 3) * 2;
    const int mA  = m0 + r_, mB = mA + 8;
    const int skip_base = Tout - SKIP_T;
    float* xbo = xout + (size_t)b * TMAX * C;   // [t][c]

    // ---------------- phase 2a: R = Wres @ G -> stash in smem [t][132] ----------------
    {
        float acc[8][4];
        #pragma unroll
        for (int j = 0; j < 8; j++)
            #pragma unroll
            for (int q = 0; q < 4; q++) acc[j][q] = 0.f;

        const uint4* rp = Rf + ((mt * 32 + lane) << 1);
        Frag wH = ldfrag(rp), wL = ldfrag(rp + 1);
        for (int ks = 0; ks < 8; ks++) {
            Frag nH, nL;
            if (ks < 7) {
                const uint4* np = Rf + ((((ks + 1) * 8 + mt) * 32 + lane) << 1);
                nH = ldfrag(np); nL = ldfrag(np + 1);
            }
            const int g = ks >> 2, kk = ks & 3;
            const uint32_t cbh = sbase + SM_GH + g * 8192;
            const uint32_t cbl = sbase + SM_GL + g * 8192;
            #pragma unroll
            for (int jp = 0; jp < 4; jp++) {
                uint32_t off = ((jp * 16 + lrow) << 7) + (kk << 5) + (lcol << 4);
                uint32_t bh[4], bl[4];
                ldsm_x4(bh, cbh + SWZ(off));
                ldsm_x4(bl, cbl + SWZ(off));
                mma_bf16(acc[2*jp],     wH.a, bh);
                mma_bf16(acc[2*jp + 1], wH.a, bh + 2);
                mma_bf16(acc[2*jp],     wH.a, bl);
                mma_bf16(acc[2*jp + 1], wH.a, bl + 2);
                mma_bf16(acc[2*jp],     wL.a, bh);
                mma_bf16(acc[2*jp + 1], wL.a, bh + 2);
            }
            wH = nH; wL = nL;
        }
        float* st = (float*)(smem + SM_ACCR);
        #pragma unroll
        for (int j = 0; j < 8; j++) {
            #pragma unroll
            for (int e = 0; e < 2; e++) {
                int tl = j * 8 + c2_ + e;
                st[tl * 132 + mA] = acc[j][e];
                st[tl * 132 + mB] = acc[j][2 + e];
            }
        }
    }

    // ---------------- phase 2b: S = Wskip @ G ----------------
    float accS[8][4];
    {
        #pragma unroll
        for (int j = 0; j < 8; j++)
            #pragma unroll
            for (int q = 0; q < 4; q++) accS[j][q] = 0.f;

        const uint4* sp = Sf + ((mt * 32 + lane) << 1);
        Frag wH = ldfrag(sp), wL = ldfrag(sp + 1);
        for (int ks = 0; ks < 8; ks++) {
            Frag nH, nL;
            if (ks < 7) {
                const uint4* np = Sf + ((((ks + 1) * 8 + mt) * 32 + lane) << 1);
                nH = ldfrag(np); nL = ldfrag(np + 1);
            }
            const int g = ks >> 2, kk = ks & 3;
            const uint32_t cbh = sbase + SM_GH + g * 8192;
            const uint32_t cbl = sbase + SM_GL + g * 8192;
            #pragma unroll
            for (int jp = 0; jp < 4; jp++) {
                uint32_t off = ((jp * 16 + lrow) << 7) + (kk << 5) + (lcol << 4);
                uint32_t bh[4], bl[4];
                ldsm_x4(bh, cbh + SWZ(off));
                ldsm_x4(bl, cbl + SWZ(off));
                mma_bf16(accS[2*jp],     wH.a, bh);
                mma_bf16(accS[2*jp + 1], wH.a, bh + 2);
                mma_bf16(accS[2*jp],     wH.a, bl);
                mma_bf16(accS[2*jp + 1], wH.a, bl + 2);
                mma_bf16(accS[2*jp],     wL.a, bh);
                mma_bf16(accS[2*jp + 1], wL.a, bh + 2);
            }
            wH = nH; wL = nL;
        }
    }
    __syncthreads();   // all G reads + accR stash done -> G region reusable

    // stash accS -> smem [m][68] f32
    {
        float* st = (float*)(smem + SM_ACCS);
        #pragma unroll
        for (int j = 0; j < 8; j++) {
            #pragma unroll
            for (int e = 0; e < 2; e++) {
                int tl = j * 8 + c2_ + e;
                st[mA * 68 + tl] = accS[j][e];
                st[mB * 68 + tl] = accS[j][2 + e];
            }
        }
    }
    __syncthreads();

    // ---------------- cooperative coalesced epilogue ----------------
    // xout: rows t0..t0+63, 8 threads/row, 16 floats/thread
    {
        const float* accR = (const float*)(smem + SM_ACCR);
        const float* bvec = (const float*)(smem + SM_BIAS);
        #pragma unroll
        for (int iter = 0; iter < 2; iter++) {
            int row = iter * 32 + (tid >> 3);
            int col = (tid & 7) * 16;
            int tt = t0 + row;
            if (tt < Tout) {
                const float* src = accR + row * 132 + col;
                const float* xr  = xbt + (size_t)(tt + d) * C + col;
                float* xo = xbo + (size_t)tt * C + col;
                #pragma unroll
                for (int j = 0; j < 4; j++) {
                    float4 a  = *(const float4*)(src + j * 4);
                    float4 rr = __ldg((const float4*)(xr + j * 4));
                    float4 bb = *(const float4*)(bvec + col + j * 4);
                    a.x += bb.x + rr.x; a.y += bb.y + rr.y;
                    a.z += bb.z + rr.z; a.w += bb.w + rr.w;
                    *(float4*)(xo + j * 4) = a;
                }
            }
        }
    }
    // skip: 128 m rows, 16 lanes/row covering 64 t
    {
        const float* accS_s = (const float*)(smem + SM_ACCS);
        const float* bvec = (const float*)(smem + SM_BIAS + 512);
        const bool aligned = ((Tout & 3) == 0);
        const int l16 = tid & 15;
        #pragma unroll
        for (int i = 0; i < 8; i++) {
            int m = i * 16 + (tid >> 4);
            float bs = bvec[m];
            const float* src = accS_s + m * 68 + l16 * 4;
            float* so = skip_out + ((size_t)b * C + m) * SKIP_T;
            int tt = t0 + l16 * 4;
            int ts = tt - skip_base;
            float4 v = *(const float4*)src;
            v.x += bs; v.y += bs; v.z += bs; v.w += bs;
            if (aligned && ts >= 0 && tt + 3 < Tout) {
                *(float4*)(so + ts) = v;
            } else {
                const float* vv = (const float*)&v;
                #pragma unroll
                for (int e = 0; e < 4; e++) {
                    int t2 = tt + e, ts2 = t2 - skip_base;
                    if (ts2 >= 0 && t2 < Tout) so[ts2] = vv[e];
                }
            }
        }
    }
}

// ======================= host =======================
static const int DIL[NB] = {
    1, 2, 4, 8, 16, 32, 64, 128, 256, 512,
    1, 2, 4, 8, 16, 32, 64, 128, 256, 512,
    1, 2, 4, 8, 16, 32, 64, 128, 256, 512,
    1, 2, 4, 8, 16, 32, 64, 128, 256, 512
};

extern "C" void kernel_launch(void* const* d_in, const int* in_sizes, int n_in,
                              void* d_out, int out_size)
{
    const float* x      = (const float*)d_in[0];
    const float* w_dil  = (const float*)d_in[1];
    const float* w_res  = (const float*)d_in[2];
    const float* b_res  = (const float*)d_in[3];
    const float* w_skip = (const float*)d_in[4];
    const float* b_skip = (const float*)d_in[5];
    float* out = (float*)d_out;

    float *xb0, *xb1;
    uint4 *wAf, *wRf, *wSf;
    cudaGetSymbolAddress((void**)&xb0, g_x0);
    cudaGetSymbolAddress((void**)&xb1, g_x1);
    cudaGetSymbolAddress((void**)&wAf, g_wAf);
    cudaGetSymbolAddress((void**)&wRf, g_wRf);
    cudaGetSymbolAddress((void**)&wSf, g_wSf);

    cudaFuncSetAttribute(wn_hmma, cudaFuncAttributeMaxDynamicSharedMemorySize, SMEM_SZ);

    {
        int total = NB * 16 * 8 * 32;
        prep_frags<<<(total + 255) / 256, 256>>>(w_dil, w_res, w_skip);
    }
    {
        dim3 g(TMAX / 32, C / 32, BATCH);
        transpose_in<<<g, dim3(32, 8)>>>(x, xb0);
    }

    int Tin = TMAX;
    const float* cur = xb0;
    for (int L = 0; L < NB; L++) {
        int dd   = DIL[L];
        int Tout = Tin - dd;
        float* xo = (L & 1) ? xb0 : xb1;
        dim3 grid((Tout + TN - 1) / TN, BATCH);
        wn_hmma<<<grid, 256, SMEM_SZ>>>(
            cur, xo,
            wAf + (size_t)L * 16 * 8 * 32 * 2,
            wRf + (size_t)L *  8 * 8 * 32 * 2,
            wSf + (size_t)L *  8 * 8 * 32 * 2,
            b_res + (size_t)L * C,
            b_skip + (size_t)L * C,
            out + (size_t)L * BATCH * C * SKIP_T,
            dd, Tin, Tout);
        cur = xo;
        Tin = Tout;
    }
}